// round 6
// baseline (speedup 1.0000x reference)
#include <cuda_runtime.h>
#include <math.h>

#define MEM_LEN 131072
#define IN_DIM  256
#define OUT_DIM 512
#define BETA    1.0f

// Scratch: device globals (no allocation allowed).
__device__ __align__(16) float g_enc[OUT_DIM];
__device__ unsigned int g_min_bits;

// ---------------------------------------------------------------------------
// k_enc: normalize x, GEMV (256x512), log_softmax -> g_enc. Also resets g_min.
// One block, 512 threads (one per output column).
// ---------------------------------------------------------------------------
__global__ void k_enc(const float* __restrict__ x,
                      const float* __restrict__ W,
                      const float* __restrict__ b,
                      const float* __restrict__ mean,
                      const float* __restrict__ stdv) {
    __shared__ float s_new[IN_DIM];
    __shared__ float s_red[16];
    __shared__ float s_bcast;

    int t = threadIdx.x;            // 0..511
    int lane = t & 31;
    int warp = t >> 5;              // 0..15

    if (t < IN_DIM) {
        float s = stdv[t];
        s_new[t] = (s == 0.0f) ? 0.0f : (x[t] - mean[t]) / s;
    }
    if (t == 0) g_min_bits = 0x7f800000u;  // +inf
    __syncthreads();

    // GEMV: logits[t] = sum_k s_new[k] * W[k*OUT_DIM + t] + b[t]
    float acc = b[t];
    #pragma unroll 8
    for (int k = 0; k < IN_DIM; k++) {
        acc = fmaf(s_new[k], __ldg(&W[k * OUT_DIM + t]), acc);
    }

    // Block max
    float m = acc;
    #pragma unroll
    for (int o = 16; o; o >>= 1) m = fmaxf(m, __shfl_xor_sync(0xffffffffu, m, o));
    if (lane == 0) s_red[warp] = m;
    __syncthreads();
    if (t < 32) {
        float v = (t < 16) ? s_red[t] : -INFINITY;
        #pragma unroll
        for (int o = 8; o; o >>= 1) v = fmaxf(v, __shfl_xor_sync(0xffffffffu, v, o));
        if (t == 0) s_bcast = v;
    }
    __syncthreads();
    float mx = s_bcast;

    // Block sum of exp
    float e = __expf(acc - mx);
    float ssum = e;
    #pragma unroll
    for (int o = 16; o; o >>= 1) ssum += __shfl_xor_sync(0xffffffffu, ssum, o);
    if (lane == 0) s_red[warp] = ssum;
    __syncthreads();
    if (t < 32) {
        float v = (t < 16) ? s_red[t] : 0.0f;
        #pragma unroll
        for (int o = 8; o; o >>= 1) v += __shfl_xor_sync(0xffffffffu, v, o);
        if (t == 0) s_bcast = v;
    }
    __syncthreads();

    g_enc[t] = acc - mx - logf(s_bcast);
}

// ---------------------------------------------------------------------------
// k_dist: warp-per-row. Fused: L1 distance to g_enc + copy memory row to out.
// blockDim 256 (8 warps -> 8 rows per block), grid = MEM_LEN/8.
// Loads are float4-aligned (input); stores are scalar (out+1 is misaligned);
// L2 write-merge reassembles full lines.
// ---------------------------------------------------------------------------
__global__ void k_dist(const float* __restrict__ mem, float* __restrict__ out_mem) {
    int lane = threadIdx.x & 31;
    int warp = threadIdx.x >> 5;
    int row  = blockIdx.x * 8 + warp;

    const float4* encv = (const float4*)g_enc;           // 128 float4
    float4 e0 = encv[lane +  0];
    float4 e1 = encv[lane + 32];
    float4 e2 = encv[lane + 64];
    float4 e3 = encv[lane + 96];

    const float4* mrow = (const float4*)(mem + (size_t)row * OUT_DIM);
    float4 m0 = __ldg(&mrow[lane +  0]);
    float4 m1 = __ldg(&mrow[lane + 32]);
    float4 m2 = __ldg(&mrow[lane + 64]);
    float4 m3 = __ldg(&mrow[lane + 96]);

    float d = 0.0f;
    d += fabsf(m0.x - e0.x) + fabsf(m0.y - e0.y) + fabsf(m0.z - e0.z) + fabsf(m0.w - e0.w);
    d += fabsf(m1.x - e1.x) + fabsf(m1.y - e1.y) + fabsf(m1.z - e1.z) + fabsf(m1.w - e1.w);
    d += fabsf(m2.x - e2.x) + fabsf(m2.y - e2.y) + fabsf(m2.z - e2.z) + fabsf(m2.w - e2.w);
    d += fabsf(m3.x - e3.x) + fabsf(m3.y - e3.y) + fabsf(m3.z - e3.z) + fabsf(m3.w - e3.w);

    // Copy row to output (scalar stores; region base is 4B-misaligned).
    float* orow = out_mem + (size_t)row * OUT_DIM;
    {
        int c = 4 * lane;
        orow[c +   0] = m0.x; orow[c +   1] = m0.y; orow[c +   2] = m0.z; orow[c +   3] = m0.w;
        orow[c + 128] = m1.x; orow[c + 129] = m1.y; orow[c + 130] = m1.z; orow[c + 131] = m1.w;
        orow[c + 256] = m2.x; orow[c + 257] = m2.y; orow[c + 258] = m2.z; orow[c + 259] = m2.w;
        orow[c + 384] = m3.x; orow[c + 385] = m3.y; orow[c + 386] = m3.z; orow[c + 387] = m3.w;
    }

    // Warp sum of d, then block min, one atomic per block.
    #pragma unroll
    for (int o = 16; o; o >>= 1) d += __shfl_xor_sync(0xffffffffu, d, o);

    __shared__ float s_d[8];
    if (lane == 0) s_d[warp] = d;
    __syncthreads();
    if (threadIdx.x == 0) {
        float mn = s_d[0];
        #pragma unroll
        for (int i = 1; i < 8; i++) mn = fminf(mn, s_d[i]);
        // dist >= 0 so float order == uint order
        atomicMin(&g_min_bits, __float_as_uint(mn));
    }
}

// ---------------------------------------------------------------------------
// k_copy: mem_data -> out (float4 loads, scalar stores into misaligned region)
// ---------------------------------------------------------------------------
__global__ void k_copy(const float* __restrict__ src, float* __restrict__ dst, size_t n4) {
    size_t i = (size_t)blockIdx.x * blockDim.x + threadIdx.x;
    size_t stride = (size_t)gridDim.x * blockDim.x;
    for (; i < n4; i += stride) {
        float4 v = __ldg(&((const float4*)src)[i]);
        float* d = dst + 4 * i;
        d[0] = v.x; d[1] = v.y; d[2] = v.z; d[3] = v.w;
    }
}

// ---------------------------------------------------------------------------
// k_fin: write loss; conditional single-row update of memory and mem_data.
// ---------------------------------------------------------------------------
__global__ void k_fin(const float* __restrict__ x, const int* __restrict__ count,
                      float* __restrict__ out) {
    float loss = __uint_as_float(g_min_bits);
    int t = threadIdx.x;
    if (t == 0) out[0] = loss;
    if (loss <= BETA) {
        int pos = count[0] % MEM_LEN;
        float* out_mem = out + 1;
        float* out_md  = out + 1 + (size_t)MEM_LEN * OUT_DIM;
        if (t < OUT_DIM) out_mem[(size_t)pos * OUT_DIM + t] = g_enc[t];
        if (t < IN_DIM)  out_md[(size_t)pos * IN_DIM + t]   = x[t];
    }
}

// ---------------------------------------------------------------------------
extern "C" void kernel_launch(void* const* d_in, const int* in_sizes, int n_in,
                              void* d_out, int out_size) {
    const float* x    = (const float*)d_in[0];
    const float* W    = (const float*)d_in[1];
    const float* b    = (const float*)d_in[2];
    const float* mem  = (const float*)d_in[3];
    const float* md   = (const float*)d_in[4];
    const float* mean = (const float*)d_in[5];
    const float* stdv = (const float*)d_in[6];
    const int*   cnt  = (const int*)d_in[7];
    float* out = (float*)d_out;

    float* out_mem = out + 1;
    float* out_md  = out + 1 + (size_t)MEM_LEN * OUT_DIM;

    k_enc<<<1, 512>>>(x, W, b, mean, stdv);
    k_dist<<<MEM_LEN / 8, 256>>>(mem, out_mem);
    k_copy<<<8192, 256>>>(md, out_md, (size_t)MEM_LEN * IN_DIM / 4);
    k_fin<<<1, 512>>>(x, cnt, out);
}

// round 7
// speedup vs baseline: 1.0566x; 1.0566x over previous
#include <cuda_runtime.h>
#include <math.h>

#define MEM_LEN 131072
#define IN_DIM  256
#define OUT_DIM 512
#define BETA    1.0f

// Scratch: device globals (no allocation allowed).
__device__ __align__(16) float g_enc[OUT_DIM];
__device__ unsigned int g_min_bits;

// ---------------------------------------------------------------------------
// k_enc: normalize x, GEMV (256x512), log_softmax -> g_enc. Also resets g_min.
// One block, 512 threads (one per output column).
// ---------------------------------------------------------------------------
__global__ void k_enc(const float* __restrict__ x,
                      const float* __restrict__ W,
                      const float* __restrict__ b,
                      const float* __restrict__ mean,
                      const float* __restrict__ stdv) {
    __shared__ float s_new[IN_DIM];
    __shared__ float s_red[16];
    __shared__ float s_bcast;

    int t = threadIdx.x;            // 0..511
    int lane = t & 31;
    int warp = t >> 5;              // 0..15

    if (t < IN_DIM) {
        float s = stdv[t];
        s_new[t] = (s == 0.0f) ? 0.0f : (x[t] - mean[t]) / s;
    }
    if (t == 0) g_min_bits = 0x7f800000u;  // +inf
    __syncthreads();

    // GEMV: logits[t] = sum_k s_new[k] * W[k*OUT_DIM + t] + b[t]
    float acc = b[t];
    #pragma unroll 16
    for (int k = 0; k < IN_DIM; k++) {
        acc = fmaf(s_new[k], __ldg(&W[k * OUT_DIM + t]), acc);
    }

    // Block max
    float m = acc;
    #pragma unroll
    for (int o = 16; o; o >>= 1) m = fmaxf(m, __shfl_xor_sync(0xffffffffu, m, o));
    if (lane == 0) s_red[warp] = m;
    __syncthreads();
    if (t < 32) {
        float v = (t < 16) ? s_red[t] : -INFINITY;
        #pragma unroll
        for (int o = 8; o; o >>= 1) v = fmaxf(v, __shfl_xor_sync(0xffffffffu, v, o));
        if (t == 0) s_bcast = v;
    }
    __syncthreads();
    float mx = s_bcast;

    // Block sum of exp
    float e = __expf(acc - mx);
    float ssum = e;
    #pragma unroll
    for (int o = 16; o; o >>= 1) ssum += __shfl_xor_sync(0xffffffffu, ssum, o);
    if (lane == 0) s_red[warp] = ssum;
    __syncthreads();
    if (t < 32) {
        float v = (t < 16) ? s_red[t] : 0.0f;
        #pragma unroll
        for (int o = 8; o; o >>= 1) v += __shfl_xor_sync(0xffffffffu, v, o);
        if (t == 0) s_bcast = v;
    }
    __syncthreads();

    g_enc[t] = acc - mx - logf(s_bcast);
}

// ---------------------------------------------------------------------------
// k_dist: warp-per-row, STRIDED element mapping (lane + 32*i).
// Every LDG.32 / STG.32 instruction is 128B contiguous across the warp, so
// store sector efficiency is ~100% even though the output base is 4B-offset.
// blockDim 256 (8 warps -> 8 rows per block), grid = MEM_LEN/8.
// ---------------------------------------------------------------------------
__global__ void k_dist(const float* __restrict__ mem, float* __restrict__ out_mem) {
    __shared__ float s_enc[OUT_DIM];
    __shared__ float s_d[8];

    int lane = threadIdx.x & 31;
    int warp = threadIdx.x >> 5;
    int row  = blockIdx.x * 8 + warp;

    // Stage enc in shared (512 floats, 256 threads -> 2 each)
    s_enc[threadIdx.x]       = g_enc[threadIdx.x];
    s_enc[threadIdx.x + 256] = g_enc[threadIdx.x + 256];
    __syncthreads();

    const float* mrow = mem + (size_t)row * OUT_DIM;
    float*       orow = out_mem + (size_t)row * OUT_DIM;

    float m[16];
    #pragma unroll
    for (int i = 0; i < 16; i++)
        m[i] = __ldg(&mrow[lane + 32 * i]);

    float d = 0.0f;
    #pragma unroll
    for (int i = 0; i < 16; i++)
        d += fabsf(m[i] - s_enc[lane + 32 * i]);

    #pragma unroll
    for (int i = 0; i < 16; i++)
        orow[lane + 32 * i] = m[i];

    // Warp sum of d, then block min, one atomic per block.
    #pragma unroll
    for (int o = 16; o; o >>= 1) d += __shfl_xor_sync(0xffffffffu, d, o);

    if (lane == 0) s_d[warp] = d;
    __syncthreads();
    if (threadIdx.x == 0) {
        float mn = s_d[0];
        #pragma unroll
        for (int i = 1; i < 8; i++) mn = fminf(mn, s_d[i]);
        // dist >= 0 so float order == uint order
        atomicMin(&g_min_bits, __float_as_uint(mn));
    }
}

// ---------------------------------------------------------------------------
// k_copy: mem_data -> out. Each block owns a contiguous 4096-float chunk;
// each of the 16 iterations is a fully coalesced 1024B load + store.
// ---------------------------------------------------------------------------
__global__ void k_copy(const float* __restrict__ src, float* __restrict__ dst) {
    size_t base = (size_t)blockIdx.x * 4096 + threadIdx.x;
    float v[16];
    #pragma unroll
    for (int j = 0; j < 16; j++)
        v[j] = __ldg(&src[base + 256 * j]);
    #pragma unroll
    for (int j = 0; j < 16; j++)
        dst[base + 256 * j] = v[j];
}

// ---------------------------------------------------------------------------
// k_fin: write loss; conditional single-row update of memory and mem_data.
// ---------------------------------------------------------------------------
__global__ void k_fin(const float* __restrict__ x, const int* __restrict__ count,
                      float* __restrict__ out) {
    float loss = __uint_as_float(g_min_bits);
    int t = threadIdx.x;
    if (t == 0) out[0] = loss;
    if (loss <= BETA) {
        int pos = count[0] % MEM_LEN;
        float* out_mem = out + 1;
        float* out_md  = out + 1 + (size_t)MEM_LEN * OUT_DIM;
        if (t < OUT_DIM) out_mem[(size_t)pos * OUT_DIM + t] = g_enc[t];
        if (t < IN_DIM)  out_md[(size_t)pos * IN_DIM + t]   = x[t];
    }
}

// ---------------------------------------------------------------------------
extern "C" void kernel_launch(void* const* d_in, const int* in_sizes, int n_in,
                              void* d_out, int out_size) {
    const float* x    = (const float*)d_in[0];
    const float* W    = (const float*)d_in[1];
    const float* b    = (const float*)d_in[2];
    const float* mem  = (const float*)d_in[3];
    const float* md   = (const float*)d_in[4];
    const float* mean = (const float*)d_in[5];
    const float* stdv = (const float*)d_in[6];
    const int*   cnt  = (const int*)d_in[7];
    float* out = (float*)d_out;

    float* out_mem = out + 1;
    float* out_md  = out + 1 + (size_t)MEM_LEN * OUT_DIM;

    k_enc<<<1, 512>>>(x, W, b, mean, stdv);
    k_dist<<<MEM_LEN / 8, 256>>>(mem, out_mem);
    // MEM_LEN*IN_DIM = 33554432 floats / 4096 per block = 8192 blocks
    k_copy<<<8192, 256>>>(md, out_md);
    k_fin<<<1, 512>>>(x, cnt, out);
}

// round 10
// speedup vs baseline: 1.1437x; 1.0824x over previous
#include <cuda_runtime.h>
#include <math.h>

#define MEM_LEN 131072
#define IN_DIM  256
#define OUT_DIM 512
#define BETA    1.0f

#define DIST_BLOCKS  (MEM_LEN / 8)                 // 16384, 8 rows per block
#define MD_BLOCKS    (MEM_LEN * IN_DIM / 4096)     // 8192, 4096 floats per block
#define TOTAL_BLOCKS (DIST_BLOCKS + MD_BLOCKS)     // 24576

// Scratch: device globals (no allocation allowed).
__device__ __align__(16) float g_enc[OUT_DIM];
__device__ unsigned int g_min_bits;
__device__ unsigned int g_done;

// ---------------------------------------------------------------------------
// k_enc: normalize x, GEMV (256x512), log_softmax -> g_enc.
// Resets g_min_bits and g_done for this graph replay.
// One block, 512 threads. K split 4 ways x 128 float4 col-groups -> LDG.128.
// ---------------------------------------------------------------------------
__global__ void k_enc(const float* __restrict__ x,
                      const float* __restrict__ W,
                      const float* __restrict__ b,
                      const float* __restrict__ mean,
                      const float* __restrict__ stdv) {
    __shared__ float  s_new[IN_DIM];
    __shared__ float4 s_acc4[4][OUT_DIM / 4];   // [k-partition][col-group]
    __shared__ float  s_red[16];
    __shared__ float  s_bcast;

    int t = threadIdx.x;            // 0..511
    int lane = t & 31;
    int warp = t >> 5;              // 0..15

    if (t < IN_DIM) {
        float s = stdv[t];
        s_new[t] = (s == 0.0f) ? 0.0f : (x[t] - mean[t]) / s;
    }
    if (t == 0) { g_min_bits = 0x7f800000u; g_done = 0; }
    __syncthreads();

    // Partial GEMV: partition p covers k in [64p, 64p+64), col-group cg covers
    // columns 4cg..4cg+3.  W row-major [256][512] viewed as float4 [256][128].
    int cg = t & 127;
    int p  = t >> 7;
    const float4* W4 = (const float4*)W;
    float4 acc = make_float4(0.f, 0.f, 0.f, 0.f);
    int k0 = p * 64;
    #pragma unroll 8
    for (int k = 0; k < 64; k++) {
        float  s = s_new[k0 + k];
        float4 w = __ldg(&W4[(size_t)(k0 + k) * 128 + cg]);
        acc.x = fmaf(s, w.x, acc.x);
        acc.y = fmaf(s, w.y, acc.y);
        acc.z = fmaf(s, w.z, acc.z);
        acc.w = fmaf(s, w.w, acc.w);
    }
    s_acc4[p][cg] = acc;
    __syncthreads();

    // Combine partials: thread t owns column t.
    const float* s_acc = (const float*)s_acc4;   // [4][512]
    float logit = b[t] + s_acc[t] + s_acc[512 + t] + s_acc[1024 + t] + s_acc[1536 + t];

    // Block max
    float m = logit;
    #pragma unroll
    for (int o = 16; o; o >>= 1) m = fmaxf(m, __shfl_xor_sync(0xffffffffu, m, o));
    if (lane == 0) s_red[warp] = m;
    __syncthreads();
    if (t < 32) {
        float v = (t < 16) ? s_red[t] : -INFINITY;
        #pragma unroll
        for (int o = 8; o; o >>= 1) v = fmaxf(v, __shfl_xor_sync(0xffffffffu, v, o));
        if (t == 0) s_bcast = v;
    }
    __syncthreads();
    float mx = s_bcast;

    // Block sum of exp
    float ssum = __expf(logit - mx);
    #pragma unroll
    for (int o = 16; o; o >>= 1) ssum += __shfl_xor_sync(0xffffffffu, ssum, o);
    if (lane == 0) s_red[warp] = ssum;
    __syncthreads();
    if (t < 32) {
        float v = (t < 16) ? s_red[t] : 0.0f;
        #pragma unroll
        for (int o = 8; o; o >>= 1) v += __shfl_xor_sync(0xffffffffu, v, o);
        if (t == 0) s_bcast = v;
    }
    __syncthreads();

    g_enc[t] = logit - mx - logf(s_bcast);
}

// ---------------------------------------------------------------------------
// k_main: fused dist+copy (blocks [0,16384)), mem_data copy (blocks
// [16384,24576)), and last-done-block finalize (loss write + conditional
// ring-buffer row update).  All bulk traffic uses streaming cache hints.
// ---------------------------------------------------------------------------
__global__ void k_main(const float* __restrict__ mem,
                       const float* __restrict__ md,
                       const float* __restrict__ x,
                       const int*   __restrict__ count,
                       float* __restrict__ out) {
    float* out_mem = out + 1;
    float* out_md  = out + 1 + (size_t)MEM_LEN * OUT_DIM;

    int bid = blockIdx.x;

    if (bid < DIST_BLOCKS) {
        // ---- L1 distance + copy, 8 rows (one per warp) ----
        __shared__ float s_enc[OUT_DIM];
        __shared__ float s_d[8];

        int lane = threadIdx.x & 31;
        int warp = threadIdx.x >> 5;
        int row  = bid * 8 + warp;

        s_enc[threadIdx.x]       = g_enc[threadIdx.x];
        s_enc[threadIdx.x + 256] = g_enc[threadIdx.x + 256];
        __syncthreads();

        const float* mrow = mem + (size_t)row * OUT_DIM;
        float*       orow = out_mem + (size_t)row * OUT_DIM;

        float m[16];
        #pragma unroll
        for (int i = 0; i < 16; i++)
            m[i] = __ldcs(&mrow[lane + 32 * i]);

        float d = 0.0f;
        #pragma unroll
        for (int i = 0; i < 16; i++)
            d += fabsf(m[i] - s_enc[lane + 32 * i]);

        #pragma unroll
        for (int i = 0; i < 16; i++)
            __stcs(&orow[lane + 32 * i], m[i]);

        #pragma unroll
        for (int o = 16; o; o >>= 1) d += __shfl_xor_sync(0xffffffffu, d, o);
        if (lane == 0) s_d[warp] = d;
        __syncthreads();
        if (threadIdx.x == 0) {
            float mn = s_d[0];
            #pragma unroll
            for (int i = 1; i < 8; i++) mn = fminf(mn, s_d[i]);
            atomicMin(&g_min_bits, __float_as_uint(mn));   // d >= 0: float order == uint order
        }
    } else {
        // ---- mem_data copy: contiguous 4096-float chunk ----
        size_t base = (size_t)(bid - DIST_BLOCKS) * 4096 + threadIdx.x;
        float v[16];
        #pragma unroll
        for (int j = 0; j < 16; j++)
            v[j] = __ldcs(&md[base + 256 * j]);
        #pragma unroll
        for (int j = 0; j < 16; j++)
            __stcs(&out_md[base + 256 * j], v[j]);
    }

    // ---- last-done-block finalize ----
    __shared__ int s_last;
    __syncthreads();
    if (threadIdx.x == 0) {
        __threadfence();
        unsigned int ticket = atomicAdd(&g_done, 1u);
        s_last = (ticket == TOTAL_BLOCKS - 1u);
    }
    __syncthreads();

    if (s_last) {
        float loss = __uint_as_float(atomicOr(&g_min_bits, 0u));
        int t = threadIdx.x;
        if (t == 0) out[0] = loss;
        if (loss <= BETA) {
            int pos = count[0] % MEM_LEN;
            // overwrite slot pos with enc / x (stores ordered after all copy
            // blocks' stores by the fence+ticket protocol)
            out_mem[(size_t)pos * OUT_DIM + t]       = g_enc[t];
            out_mem[(size_t)pos * OUT_DIM + t + 256] = g_enc[t + 256];
            out_md[(size_t)pos * IN_DIM + t]         = x[t];
        }
    }
}

// ---------------------------------------------------------------------------
extern "C" void kernel_launch(void* const* d_in, const int* in_sizes, int n_in,
                              void* d_out, int out_size) {
    const float* x    = (const float*)d_in[0];
    const float* W    = (const float*)d_in[1];
    const float* b    = (const float*)d_in[2];
    const float* mem  = (const float*)d_in[3];
    const float* md   = (const float*)d_in[4];
    const float* mean = (const float*)d_in[5];
    const float* stdv = (const float*)d_in[6];
    const int*   cnt  = (const int*)d_in[7];
    float* out = (float*)d_out;

    k_enc<<<1, 512>>>(x, W, b, mean, stdv);
    k_main<<<TOTAL_BLOCKS, 256>>>(mem, md, x, cnt, out);
}

// round 12
// speedup vs baseline: 1.1988x; 1.0481x over previous
#include <cuda_runtime.h>
#include <math.h>

#define MEM_LEN 131072
#define IN_DIM  256
#define OUT_DIM 512
#define BETA    1.0f

#define DIST_BLOCKS  (MEM_LEN / 8)                 // 16384, 8 rows per block
#define MD_BLOCKS    (MEM_LEN * IN_DIM / 4096)     // 8192, 4096 floats per block
#define TOTAL_BLOCKS (1 + MD_BLOCKS + DIST_BLOCKS) // 24577 (bid 0 = encoder)

// Scratch: device globals (no allocation allowed). Statically initialized for
// the first call; the finalize block resets them for every subsequent graph
// replay (self-cleaning => deterministic).
__device__ __align__(16) float g_enc[OUT_DIM];
__device__ unsigned int g_min_bits = 0x7f800000u;  // +inf
__device__ unsigned int g_done     = 0;
__device__ unsigned int g_flag     = 0;

// ---------------------------------------------------------------------------
// Encoder, executed by block 0 (256 threads): normalize x, GEMV (256x512),
// log_softmax -> g_enc. 512 GEMV tasks (4 k-partitions x 128 float4
// col-groups); each thread does 2 tasks. Softmax: 2 columns per thread.
// ---------------------------------------------------------------------------
__device__ void enc_block(const float* __restrict__ x,
                          const float* __restrict__ W,
                          const float* __restrict__ b,
                          const float* __restrict__ mean,
                          const float* __restrict__ stdv) {
    __shared__ float  s_new[IN_DIM];
    __shared__ float4 s_acc4[4][OUT_DIM / 4];   // [k-partition][col-group]
    __shared__ float  s_red[8];
    __shared__ float  s_bcast;

    int t = threadIdx.x;            // 0..255
    int lane = t & 31;
    int warp = t >> 5;              // 0..7

    {
        float s = stdv[t];
        s_new[t] = (s == 0.0f) ? 0.0f : (x[t] - mean[t]) / s;
    }
    __syncthreads();

    const float4* W4 = (const float4*)W;   // [256][128]
    #pragma unroll
    for (int task = 0; task < 2; task++) {
        int id = t + 256 * task;           // 0..511
        int cg = id & 127;                 // float4 column group
        int p  = id >> 7;                  // k-partition (64 k each)
        int k0 = p * 64;
        float4 acc = make_float4(0.f, 0.f, 0.f, 0.f);
        #pragma unroll 8
        for (int k = 0; k < 64; k++) {
            float  s = s_new[k0 + k];
            float4 w = __ldg(&W4[(size_t)(k0 + k) * 128 + cg]);
            acc.x = fmaf(s, w.x, acc.x);
            acc.y = fmaf(s, w.y, acc.y);
            acc.z = fmaf(s, w.z, acc.z);
            acc.w = fmaf(s, w.w, acc.w);
        }
        s_acc4[p][cg] = acc;
    }
    __syncthreads();

    // Thread t owns columns t and t+256.
    const float* s_acc = (const float*)s_acc4;   // [4][512]
    float l0 = b[t]       + s_acc[t]       + s_acc[512 + t]       + s_acc[1024 + t]       + s_acc[1536 + t];
    float l1 = b[t + 256] + s_acc[t + 256] + s_acc[512 + t + 256] + s_acc[1024 + t + 256] + s_acc[1536 + t + 256];

    // Block max over 512 logits
    float m = fmaxf(l0, l1);
    #pragma unroll
    for (int o = 16; o; o >>= 1) m = fmaxf(m, __shfl_xor_sync(0xffffffffu, m, o));
    if (lane == 0) s_red[warp] = m;
    __syncthreads();
    if (t < 32) {
        float v = (t < 8) ? s_red[t] : -INFINITY;
        #pragma unroll
        for (int o = 4; o; o >>= 1) v = fmaxf(v, __shfl_xor_sync(0xffffffffu, v, o));
        if (t == 0) s_bcast = v;
    }
    __syncthreads();
    float mx = s_bcast;

    // Block sum of exp
    float ssum = __expf(l0 - mx) + __expf(l1 - mx);
    #pragma unroll
    for (int o = 16; o; o >>= 1) ssum += __shfl_xor_sync(0xffffffffu, ssum, o);
    if (lane == 0) s_red[warp] = ssum;
    __syncthreads();
    if (t < 32) {
        float v = (t < 8) ? s_red[t] : 0.0f;
        #pragma unroll
        for (int o = 4; o; o >>= 1) v += __shfl_xor_sync(0xffffffffu, v, o);
        if (t == 0) s_bcast = v;
    }
    __syncthreads();
    float ls = logf(s_bcast);

    g_enc[t]       = l0 - mx - ls;
    g_enc[t + 256] = l1 - mx - ls;
    __threadfence();
    if (t == 0) atomicExch(&g_flag, 1u);   // publish
}

// ---------------------------------------------------------------------------
// k_all: ONE kernel.
//   bid 0                        : encoder (publishes g_enc via g_flag)
//   bid 1 .. MD_BLOCKS           : mem_data copy (independent of enc; these
//                                  fill the first ~7 waves and hide enc)
//   bid MD_BLOCKS+1 .. end       : L1-dist + memory copy (spin on g_flag,
//                                  which is set long before they schedule)
// Last-done block (ticket) writes loss, does the conditional row update, and
// resets the globals for the next graph replay.
// ---------------------------------------------------------------------------
__global__ void __launch_bounds__(256) k_all(
        const float* __restrict__ mem,
        const float* __restrict__ md,
        const float* __restrict__ x,
        const float* __restrict__ W,
        const float* __restrict__ b,
        const float* __restrict__ mean,
        const float* __restrict__ stdv,
        const int*   __restrict__ count,
        float* __restrict__ out) {
    float* out_mem = out + 1;
    float* out_md  = out + 1 + (size_t)MEM_LEN * OUT_DIM;

    int bid = blockIdx.x;

    if (bid == 0) {
        enc_block(x, W, b, mean, stdv);
    } else if (bid <= MD_BLOCKS) {
        // ---- mem_data copy: contiguous 4096-float chunk ----
        size_t base = (size_t)(bid - 1) * 4096 + threadIdx.x;
        float v[16];
        #pragma unroll
        for (int j = 0; j < 16; j++)
            v[j] = __ldcs(&md[base + 256 * j]);
        #pragma unroll
        for (int j = 0; j < 16; j++)
            __stcs(&out_md[base + 256 * j], v[j]);
    } else {
        // ---- L1 distance + copy, 8 rows (one per warp) ----
        __shared__ float s_enc[OUT_DIM];
        __shared__ float s_d[8];

        int lane = threadIdx.x & 31;
        int warp = threadIdx.x >> 5;
        int row  = (bid - 1 - MD_BLOCKS) * 8 + warp;

        // Wait for encoder (normally already done many waves ago).
        if (threadIdx.x == 0) {
            while (atomicAdd(&g_flag, 0u) == 0u) { __nanosleep(128); }
        }
        __syncthreads();

        // Stage enc in shared (L2 hits; bypass L1 for acquire safety).
        s_enc[threadIdx.x]       = __ldcg(&g_enc[threadIdx.x]);
        s_enc[threadIdx.x + 256] = __ldcg(&g_enc[threadIdx.x + 256]);
        __syncthreads();

        const float* mrow = mem + (size_t)row * OUT_DIM;
        float*       orow = out_mem + (size_t)row * OUT_DIM;

        float m[16];
        #pragma unroll
        for (int i = 0; i < 16; i++)
            m[i] = __ldcs(&mrow[lane + 32 * i]);

        float d = 0.0f;
        #pragma unroll
        for (int i = 0; i < 16; i++)
            d += fabsf(m[i] - s_enc[lane + 32 * i]);

        #pragma unroll
        for (int i = 0; i < 16; i++)
            __stcs(&orow[lane + 32 * i], m[i]);

        #pragma unroll
        for (int o = 16; o; o >>= 1) d += __shfl_xor_sync(0xffffffffu, d, o);
        if (lane == 0) s_d[warp] = d;
        __syncthreads();
        if (threadIdx.x == 0) {
            float mn = s_d[0];
            #pragma unroll
            for (int i = 1; i < 8; i++) mn = fminf(mn, s_d[i]);
            atomicMin(&g_min_bits, __float_as_uint(mn));   // d >= 0: float order == uint order
        }
    }

    // ---- last-done-block finalize ----
    __shared__ int s_last;
    __syncthreads();
    if (threadIdx.x == 0) {
        __threadfence();
        unsigned int ticket = atomicAdd(&g_done, 1u);
        s_last = (ticket == (unsigned)(TOTAL_BLOCKS - 1));
    }
    __syncthreads();

    if (s_last) {
        float loss = __uint_as_float(atomicAdd(&g_min_bits, 0u));
        int t = threadIdx.x;
        if (t == 0) out[0] = loss;
        if (loss <= BETA) {
            int pos = count[0] % MEM_LEN;
            out_mem[(size_t)pos * OUT_DIM + t]       = __ldcg(&g_enc[t]);
            out_mem[(size_t)pos * OUT_DIM + t + 256] = __ldcg(&g_enc[t + 256]);
            out_md[(size_t)pos * IN_DIM + t]         = x[t];
        }
        // Reset globals for the next graph replay (deterministic self-clean).
        __syncthreads();
        if (t == 0) {
            g_min_bits = 0x7f800000u;
            g_done     = 0u;
            atomicExch(&g_flag, 0u);
            __threadfence();
        }
    }
}

// ---------------------------------------------------------------------------
extern "C" void kernel_launch(void* const* d_in, const int* in_sizes, int n_in,
                              void* d_out, int out_size) {
    const float* x    = (const float*)d_in[0];
    const float* W    = (const float*)d_in[1];
    const float* b    = (const float*)d_in[2];
    const float* mem  = (const float*)d_in[3];
    const float* md   = (const float*)d_in[4];
    const float* mean = (const float*)d_in[5];
    const float* stdv = (const float*)d_in[6];
    const int*   cnt  = (const int*)d_in[7];
    float* out = (float*)d_out;

    k_all<<<TOTAL_BLOCKS, 256>>>(mem, md, x, W, b, mean, stdv, cnt, out);
}